// round 5
// baseline (speedup 1.0000x reference)
#include <cuda_runtime.h>
#include <cuda_fp16.h>
#include <cstdint>
#include <math.h>

#define NS   1024
#define SEQ  64
#define EDIM 256
#define HDIM 512
#define GDIM 2048
#define VOC  32000

// ---------------- device scratch ----------------
__device__ __half g_h16[2][2][2 * NS * HDIM];      // [parity][plane][dir*NS*H + n*H + k]
__device__ float  g_c   [2 * NS * HDIM];
__device__ float  g_pool[2 * NS * HDIM];
__device__ int    g_len [NS];
__device__ __half g_whh_h[2 * GDIM * HDIM], g_whh_l[2 * GDIM * HDIM];
__device__ __half g_wih_h[2 * GDIM * EDIM], g_wih_l[2 * GDIM * EDIM];
__device__ __half g_emb_h[VOC * EDIM],      g_emb_l[VOC * EDIM];

// ---------------- helpers ----------------
__device__ __forceinline__ uint32_t smem_u32(const void* ptr) {
    uint32_t a;
    asm("{ .reg .u64 t; cvta.to.shared.u64 t, %1; cvt.u32.u64 %0, t; }" : "=r"(a) : "l"(ptr));
    return a;
}
#define CP_ASYNC16(dst, src) \
    asm volatile("cp.async.cg.shared.global [%0], [%1], 16;" :: "r"(dst), "l"(src) : "memory")
#define CP_COMMIT() asm volatile("cp.async.commit_group;" ::: "memory")
#define CP_WAIT(n)  asm volatile("cp.async.wait_group %0;" :: "n"(n) : "memory")

__device__ __forceinline__ void ldsm4(uint32_t* r, uint32_t addr) {
    asm volatile("ldmatrix.sync.aligned.m8n8.x4.shared.b16 {%0,%1,%2,%3}, [%4];"
        : "=r"(r[0]), "=r"(r[1]), "=r"(r[2]), "=r"(r[3]) : "r"(addr));
}
__device__ __forceinline__ void mma16816(float* c, const uint32_t* a, const uint32_t* b) {
    asm volatile("mma.sync.aligned.m16n8k16.row.col.f32.f16.f16.f32 "
        "{%0,%1,%2,%3}, {%4,%5,%6,%7}, {%8,%9}, {%0,%1,%2,%3};"
        : "+f"(c[0]), "+f"(c[1]), "+f"(c[2]), "+f"(c[3])
        : "r"(a[0]), "r"(a[1]), "r"(a[2]), "r"(a[3]), "r"(b[0]), "r"(b[1]));
}
__device__ __forceinline__ void split2(float a, float b, uint32_t& hi, uint32_t& lo) {
    __half ha = __float2half_rn(a), hb = __float2half_rn(b);
    __half la = __float2half_rn(a - __half2float(ha));
    __half lb = __float2half_rn(b - __half2float(hb));
    __half2 H = __halves2half2(ha, hb);
    __half2 L = __halves2half2(la, lb);
    hi = *reinterpret_cast<uint32_t*>(&H);
    lo = *reinterpret_cast<uint32_t*>(&L);
}

// ---------------- smem layout ----------------
// stage: Ahi 128x80 | Alo 128x80 | Bhi 256x80 | Blo 256x80 = 61440 B; 3 stages
#define ST_SZ   61440
#define A_LO    10240
#define B_HI    20480
#define B_PL    20480
#define SM_TOK  184320
#define SM_BIAS 184832
#define SM_LEN  185856
#define SMEM_SZ 186368
#define NCH     24      // 16 h-chunks (K=512) + 8 x-chunks (K=256)
// epilogue aliases (dead stage area after final chunk):
#define EP_C    0       // float [128][68]
#define EP_P    34816   // float [128][68]
#define EP_HI   69632   // half  [128][72]
#define EP_LO   88064   // half  [128][72]

// one K32 chunk of 3-pass split-fp16 mma, warp tile 64x64
__device__ __forceinline__ void compute_chunk(float C[4][8][4], uint32_t st,
                                              uint32_t a_off, uint32_t b_off) {
    #pragma unroll
    for (int kk = 0; kk < 2; kk++) {
        uint32_t Ah[4][4], Bh[4][4];
        #pragma unroll
        for (int mf = 0; mf < 4; mf++) ldsm4(Ah[mf], st + mf * 1280 + kk * 32 + a_off);
        #pragma unroll
        for (int nq = 0; nq < 4; nq++) ldsm4(Bh[nq], st + B_HI + nq * 1280 + kk * 32 + b_off);
        #pragma unroll
        for (int mf = 0; mf < 4; mf++)
            #pragma unroll
            for (int nf = 0; nf < 8; nf++)
                mma16816(C[mf][nf], Ah[mf], &Bh[nf >> 1][(nf & 1) * 2]);
        uint32_t Al[4][4];
        #pragma unroll
        for (int mf = 0; mf < 4; mf++) ldsm4(Al[mf], st + A_LO + mf * 1280 + kk * 32 + a_off);
        #pragma unroll
        for (int mf = 0; mf < 4; mf++)
            #pragma unroll
            for (int nf = 0; nf < 8; nf++)
                mma16816(C[mf][nf], Al[mf], &Bh[nf >> 1][(nf & 1) * 2]);
        uint32_t Bl[4][4];
        #pragma unroll
        for (int nq = 0; nq < 4; nq++) ldsm4(Bl[nq], st + B_HI + B_PL + nq * 1280 + kk * 32 + b_off);
        #pragma unroll
        for (int mf = 0; mf < 4; mf++)
            #pragma unroll
            for (int nf = 0; nf < 8; nf++)
                mma16816(C[mf][nf], Ah[mf], &Bl[nf >> 1][(nf & 1) * 2]);
    }
}

// ---------------- small kernels ----------------
__global__ void k_init(const int* __restrict__ docs) {
    int idx = blockIdx.x * blockDim.x + threadIdx.x;   // 1048576
    g_c[idx] = 0.f; g_pool[idx] = 0.f;
    g_h16[0][0][idx] = __float2half(0.f);
    g_h16[0][1][idx] = __float2half(0.f);
    if (idx < NS) {
        int cnt = 0;
        #pragma unroll
        for (int t = 0; t < SEQ; t++) cnt += (docs[idx * SEQ + t] != 0);
        g_len[idx] = cnt;
    }
}
__global__ void k_prep_emb(const float* __restrict__ emb) {
    int idx = blockIdx.x * blockDim.x + threadIdx.x;   // 2048000
    float4 v = ((const float4*)emb)[idx];
    uint32_t h0, l0, h1, l1;
    split2(v.x, v.y, h0, l0); split2(v.z, v.w, h1, l1);
    ((uint2*)g_emb_h)[idx] = make_uint2(h0, h1);
    ((uint2*)g_emb_l)[idx] = make_uint2(l0, l1);
}
__global__ void k_prep_hh(const float* __restrict__ wf, const float* __restrict__ wb) {
    int idx = blockIdx.x * blockDim.x + threadIdx.x;   // 524288
    int k4 = idx & 127, p = (idx >> 7) & 2047, dir = idx >> 18;
    const float* W = dir ? wb : wf;
    float4 v = *(const float4*)(W + (size_t)((p & 3) * HDIM + (p >> 2)) * HDIM + k4 * 4);
    uint32_t h0, l0, h1, l1;
    split2(v.x, v.y, h0, l0); split2(v.z, v.w, h1, l1);
    size_t off = (size_t)(dir * GDIM + p) * HDIM + k4 * 4;
    *(uint2*)(g_whh_h + off) = make_uint2(h0, h1);
    *(uint2*)(g_whh_l + off) = make_uint2(l0, l1);
}
__global__ void k_prep_ih(const float* __restrict__ wf, const float* __restrict__ wb) {
    int idx = blockIdx.x * blockDim.x + threadIdx.x;   // 262144
    int k4 = idx & 63, p = (idx >> 6) & 2047, dir = idx >> 17;
    const float* W = dir ? wb : wf;
    float4 v = *(const float4*)(W + (size_t)((p & 3) * HDIM + (p >> 2)) * EDIM + k4 * 4);
    uint32_t h0, l0, h1, l1;
    split2(v.x, v.y, h0, l0); split2(v.z, v.w, h1, l1);
    size_t off = (size_t)(dir * GDIM + p) * EDIM + k4 * 4;
    *(uint2*)(g_wih_h + off) = make_uint2(h0, h1);
    *(uint2*)(g_wih_l + off) = make_uint2(l0, l1);
}

// ---------------- fused recurrent step ----------------
// CTA: M=128 (n), N=256 (permuted gates p=4j+g), K=768 (512 h + 256 x); grid (8,8,2)
__global__ void __launch_bounds__(256, 1) k_step(
    const int* __restrict__ docs, const float* __restrict__ b_f,
    const float* __restrict__ b_b, int step)
{
    extern __shared__ char smem[];
    const uint32_t sb = smem_u32(smem);
    const int tid = threadIdx.x;
    const int dir = blockIdx.z;
    const int n0  = blockIdx.y * 128;
    const int p0  = blockIdx.x * 256;
    const int u   = dir ? (SEQ - 1 - step) : step;

    int*   tokS  = (int*)(smem + SM_TOK);
    float* biasS = (float*)(smem + SM_BIAS);
    int*   lenS  = (int*)(smem + SM_LEN);

    const __half* __restrict__ H0 = g_h16[step & 1][0] + (size_t)dir * NS * HDIM + (size_t)n0 * HDIM;
    const __half* __restrict__ H1 = g_h16[step & 1][1] + (size_t)dir * NS * HDIM + (size_t)n0 * HDIM;
    const __half* __restrict__ WHH_H = g_whh_h + (size_t)(dir * GDIM + p0) * HDIM;
    const __half* __restrict__ WHH_L = g_whh_l + (size_t)(dir * GDIM + p0) * HDIM;
    const __half* __restrict__ WIH_H = g_wih_h + (size_t)(dir * GDIM + p0) * EDIM;
    const __half* __restrict__ WIH_L = g_wih_l + (size_t)(dir * GDIM + p0) * EDIM;
    const float*  __restrict__ bias  = dir ? b_b : b_f;

    float* __restrict__ gc = g_c    + (size_t)dir * NS * HDIM;
    float* __restrict__ gp = g_pool + (size_t)dir * NS * HDIM;
    const int j0 = p0 >> 2;

    if (tid < 128) {
        tokS[tid] = docs[(n0 + tid) * SEQ + u];
        lenS[tid] = g_len[n0 + tid];
    }
    { int p = p0 + tid; biasS[tid] = bias[(p & 3) * HDIM + (p >> 2)]; }
    __syncthreads();

    const int lane = tid & 31, w = tid >> 5;
    const int mw = w & 1, nw = w >> 1;
    const uint32_t a_off = (mw * 64 + (lane & 15)) * 80 + (lane >> 4) * 16;
    const uint32_t b_off = (nw * 64 + (lane & 7) + ((lane >> 4) << 3)) * 80 + ((lane >> 3) & 1) * 16;

    float bias0[8], bias1[8];
    const int qr = lane >> 2, c2 = (lane & 3) * 2, odd = lane & 1;
    #pragma unroll
    for (int nf = 0; nf < 8; nf++) {
        int pc = nw * 64 + nf * 8 + c2;
        bias0[nf] = biasS[pc];
        bias1[nf] = biasS[pc + 1];
    }

    float C[4][8][4];
    #pragma unroll
    for (int a = 0; a < 4; a++)
        #pragma unroll
        for (int b = 0; b < 8; b++)
            #pragma unroll
            for (int q = 0; q < 4; q++) C[a][b][q] = 0.f;

    auto fill = [&](int ch, uint32_t base) {
        if (ch < 16) {
            const int k0 = ch * 32;
            #pragma unroll
            for (int i = 0; i < 4; i++) {
                int s = tid + i * 256;
                int pl = s >> 9, rem = s & 511, r = rem >> 2, kc = rem & 3;
                const __half* src = (pl ? H1 : H0) + r * HDIM + k0 + kc * 8;
                CP_ASYNC16(base + pl * A_LO + r * 80 + kc * 16, src);
            }
            #pragma unroll
            for (int i = 0; i < 8; i++) {
                int s = tid + i * 256;
                int pl = s >> 10, rem = s & 1023, row = rem >> 2, kc = rem & 3;
                const __half* src = (pl ? WHH_L : WHH_H) + (size_t)row * HDIM + k0 + kc * 8;
                CP_ASYNC16(base + B_HI + pl * B_PL + row * 80 + kc * 16, src);
            }
        } else {
            const int k0 = (ch - 16) * 32;
            #pragma unroll
            for (int i = 0; i < 4; i++) {
                int s = tid + i * 256;
                int pl = s >> 9, rem = s & 511, r = rem >> 2, kc = rem & 3;
                const __half* src = (pl ? g_emb_l : g_emb_h) + (size_t)tokS[r] * EDIM + k0 + kc * 8;
                CP_ASYNC16(base + pl * A_LO + r * 80 + kc * 16, src);
            }
            #pragma unroll
            for (int i = 0; i < 8; i++) {
                int s = tid + i * 256;
                int pl = s >> 10, rem = s & 1023, row = rem >> 2, kc = rem & 3;
                const __half* src = (pl ? WIH_L : WIH_H) + (size_t)row * EDIM + k0 + kc * 8;
                CP_ASYNC16(base + B_HI + pl * B_PL + row * 80 + kc * 16, src);
            }
        }
    };

    // prologue: 2 stages in flight
    fill(0, sb);          CP_COMMIT();
    fill(1, sb + ST_SZ);  CP_COMMIT();

    // single-barrier 3-stage pipeline: wait -> sync -> fill(ch+2) -> compute(ch)
    uint32_t st_c = sb;                // compute stage for ch
    uint32_t st_f = sb + 2 * ST_SZ;    // fill target for ch+2
    const uint32_t st_end = sb + 3 * ST_SZ;
    #pragma unroll 1
    for (int ch = 0; ch < NCH; ch++) {
        if (ch + 1 < NCH) { CP_WAIT(1); } else { CP_WAIT(0); }
        __syncthreads();
        if (ch + 2 < NCH) {
            fill(ch + 2, st_f);
            CP_COMMIT();
        } else if (ch == NCH - 1) {
            // prefetch c/pool tiles into dead stage-0/1 smem (overlaps final compute)
            #pragma unroll
            for (int i = 0; i < 8; i++) {
                int idx = tid + i * 256;      // 0..2047
                int r = idx >> 4, q = idx & 15;
                CP_ASYNC16(sb + EP_C + r * 272 + q * 16, &gc[(size_t)(n0 + r) * HDIM + j0 + q * 4]);
                CP_ASYNC16(sb + EP_P + r * 272 + q * 16, &gp[(size_t)(n0 + r) * HDIM + j0 + q * 4]);
            }
            CP_COMMIT();
        }
        compute_chunk(C, st_c, a_off, b_off);
        st_c += ST_SZ; if (st_c == st_end) st_c = sb;
        st_f += ST_SZ; if (st_f == st_end) st_f = sb;
    }
    CP_WAIT(0);
    __syncthreads();

    // ---------------- epilogue (smem-staged, prefetched) ----------------
    float*  cS  = (float*)(smem + EP_C);     // [128][68]
    float*  pS  = (float*)(smem + EP_P);     // [128][68]
    __half* hiS = (__half*)(smem + EP_HI);   // [128][72]
    __half* loS = (__half*)(smem + EP_LO);   // [128][72]

    #pragma unroll
    for (int mf = 0; mf < 4; mf++) {            // cell update
        #pragma unroll
        for (int rh = 0; rh < 2; rh++) {
            const int rl = mw * 64 + mf * 16 + qr + rh * 8;
            const bool inlen = (u < lenS[rl]);
            #pragma unroll
            for (int nf = 0; nf < 8; nf++) {
                float y0 = C[mf][nf][rh * 2 + 0] + bias0[nf];
                float y1 = C[mf][nf][rh * 2 + 1] + bias1[nf];
                float o0 = __shfl_xor_sync(0xffffffffu, y0, 1);
                float o1 = __shfl_xor_sync(0xffffffffu, y1, 1);
                if (!odd) {
                    float si = 1.f / (1.f + expf(-y0));
                    float sf = 1.f / (1.f + expf(-y1));
                    float tg = tanhf(o0);
                    float so = 1.f / (1.f + expf(-o1));
                    int jl = (nw * 64 + nf * 8 + c2) >> 2;
                    float c = sf * cS[rl * 68 + jl] + si * tg;
                    float h = so * tanhf(c);
                    cS[rl * 68 + jl] = c;
                    if (inlen) pS[rl * 68 + jl] += h;
                    __half hh = __float2half_rn(h);
                    hiS[rl * 72 + jl] = hh;
                    loS[rl * 72 + jl] = __float2half_rn(h - __half2float(hh));
                }
            }
        }
    }
    __syncthreads();

    __half* __restrict__ NH0 = g_h16[(step + 1) & 1][0] + (size_t)dir * NS * HDIM;
    __half* __restrict__ NH1 = g_h16[(step + 1) & 1][1] + (size_t)dir * NS * HDIM;
    #pragma unroll
    for (int i = 0; i < 8; i++) {               // coalesced stores
        int idx = tid + i * 256;
        int r = idx >> 4, q = idx & 15;
        *(float4*)&gc[(size_t)(n0 + r) * HDIM + j0 + q * 4] = *(float4*)&cS[r * 68 + q * 4];
        *(float4*)&gp[(size_t)(n0 + r) * HDIM + j0 + q * 4] = *(float4*)&pS[r * 68 + q * 4];
    }
    #pragma unroll
    for (int i = 0; i < 4; i++) {
        int idx = tid + i * 256;
        int r = idx >> 3, q = idx & 7;
        *(uint4*)&NH0[(size_t)(n0 + r) * HDIM + j0 + q * 8] = *(uint4*)&hiS[r * 72 + q * 8];
        *(uint4*)&NH1[(size_t)(n0 + r) * HDIM + j0 + q * 8] = *(uint4*)&loS[r * 72 + q * 8];
    }
}

// ---------------- final: pool/len, doc mask ----------------
__global__ void k_final(const int* __restrict__ doc_lens, float* __restrict__ out) {
    int idx = blockIdx.x * blockDim.x + threadIdx.x;  // 1048576
    int j  = idx & 1023;
    int nd = idx >> 10;
    int b = nd >> 5, d = nd & 31;
    float v = 0.f;
    if (d < doc_lens[b]) {
        int dirn = j >> 9;
        int jj   = j & 511;
        int len = g_len[nd];
        float denom = (float)(len > 0 ? len : 1);
        v = g_pool[dirn * NS * HDIM + nd * HDIM + jj] / denom;
    }
    out[idx] = v;
}

extern "C" void kernel_launch(void* const* d_in, const int* in_sizes, int n_in,
                              void* d_out, int out_size)
{
    const int* docs     = (const int*)d_in[0];
    const int* doc_lens = (const int*)d_in[1];
    int base = (n_in >= 10 && in_sizes[2] == 1) ? 3 : 2;
    const float* emb   = (const float*)d_in[base + 0];
    const float* wih_f = (const float*)d_in[base + 1];
    const float* whh_f = (const float*)d_in[base + 2];
    const float* b_f   = (const float*)d_in[base + 3];
    const float* wih_b = (const float*)d_in[base + 4];
    const float* whh_b = (const float*)d_in[base + 5];
    const float* b_b   = (const float*)d_in[base + 6];
    float* out = (float*)d_out;

    cudaFuncSetAttribute(k_step, cudaFuncAttributeMaxDynamicSharedMemorySize, SMEM_SZ);

    k_init    <<<4096, 256>>>(docs);
    k_prep_emb<<<8000, 256>>>(emb);
    k_prep_ih <<<1024, 256>>>(wih_f, wih_b);
    k_prep_hh <<<2048, 256>>>(whh_f, whh_b);
    for (int t = 0; t < SEQ; t++)
        k_step<<<dim3(8, 8, 2), 256, SMEM_SZ>>>(docs, b_f, b_b, t);
    k_final   <<<4096, 256>>>(doc_lens, out);
}

// round 6
// speedup vs baseline: 1.2431x; 1.2431x over previous
#include <cuda_runtime.h>
#include <cuda_fp16.h>
#include <cstdint>
#include <math.h>

#define NS   1024
#define SEQ  64
#define EDIM 256
#define HDIM 512
#define GDIM 2048
#define VOC  32000

// ---------------- device scratch ----------------
__device__ __half g_h16[2][2][2 * NS * HDIM];      // [parity][plane][dir*NS*H + n*H + k]
__device__ float  g_c   [2 * NS * HDIM];
__device__ float  g_pool[2 * NS * HDIM];
__device__ int    g_len [NS];
__device__ __half g_whh_h[2 * GDIM * HDIM];        // weights: fp16 hi plane only (2-pass)
__device__ __half g_wih_h[2 * GDIM * EDIM];
__device__ __half g_emb_h[VOC * EDIM], g_emb_l[VOC * EDIM];

// ---------------- helpers ----------------
__device__ __forceinline__ uint32_t smem_u32(const void* ptr) {
    uint32_t a;
    asm("{ .reg .u64 t; cvta.to.shared.u64 t, %1; cvt.u32.u64 %0, t; }" : "=r"(a) : "l"(ptr));
    return a;
}
#define CP_ASYNC16(dst, src) \
    asm volatile("cp.async.cg.shared.global [%0], [%1], 16;" :: "r"(dst), "l"(src) : "memory")
#define CP_COMMIT() asm volatile("cp.async.commit_group;" ::: "memory")
#define CP_WAIT(n)  asm volatile("cp.async.wait_group %0;" :: "n"(n) : "memory")

__device__ __forceinline__ void ldsm4(uint32_t* r, uint32_t addr) {
    asm volatile("ldmatrix.sync.aligned.m8n8.x4.shared.b16 {%0,%1,%2,%3}, [%4];"
        : "=r"(r[0]), "=r"(r[1]), "=r"(r[2]), "=r"(r[3]) : "r"(addr));
}
__device__ __forceinline__ void mma16816(float* c, const uint32_t* a, const uint32_t* b) {
    asm volatile("mma.sync.aligned.m16n8k16.row.col.f32.f16.f16.f32 "
        "{%0,%1,%2,%3}, {%4,%5,%6,%7}, {%8,%9}, {%0,%1,%2,%3};"
        : "+f"(c[0]), "+f"(c[1]), "+f"(c[2]), "+f"(c[3])
        : "r"(a[0]), "r"(a[1]), "r"(a[2]), "r"(a[3]), "r"(b[0]), "r"(b[1]));
}
__device__ __forceinline__ void split2(float a, float b, uint32_t& hi, uint32_t& lo) {
    __half ha = __float2half_rn(a), hb = __float2half_rn(b);
    __half la = __float2half_rn(a - __half2float(ha));
    __half lb = __float2half_rn(b - __half2float(hb));
    __half2 H = __halves2half2(ha, hb);
    __half2 L = __halves2half2(la, lb);
    hi = *reinterpret_cast<uint32_t*>(&H);
    lo = *reinterpret_cast<uint32_t*>(&L);
}
__device__ __forceinline__ uint32_t pack_hi2(float a, float b) {
    __half2 H = __halves2half2(__float2half_rn(a), __float2half_rn(b));
    return *reinterpret_cast<uint32_t*>(&H);
}

// ---------------- smem layout ----------------
// stage: Ahi 128x80 | Alo 128x80 | Bhi 256x80 = 40960 B; 4 stages
#define ST_SZ   40960
#define A_LO    10240
#define B_HI    20480
#define SM_TOK  163840
#define SM_BIAS 164352
#define SM_LEN  165376
#define SMEM_SZ 165888
#define NCH     24      // 16 h-chunks (K=512) + 8 x-chunks (K=256)
// epilogue aliases (stages 0/1 region, dead when used):
#define EP_C    0       // float [128][68]
#define EP_P    34816   // float [128][68]
#define EP_HI   69632   // half  [128][72]  (written only after all compute done)
#define EP_LO   88064   // half  [128][72]

// one K32 chunk: 2-pass split-fp16 (A exact, B=fp16), warp tile 64x64
__device__ __forceinline__ void compute_chunk(float C[4][8][4], uint32_t st,
                                              uint32_t a_off, uint32_t b_off) {
    #pragma unroll
    for (int kk = 0; kk < 2; kk++) {
        uint32_t Ah[4][4], Bh[4][4];
        #pragma unroll
        for (int mf = 0; mf < 4; mf++) ldsm4(Ah[mf], st + mf * 1280 + kk * 32 + a_off);
        #pragma unroll
        for (int nq = 0; nq < 4; nq++) ldsm4(Bh[nq], st + B_HI + nq * 1280 + kk * 32 + b_off);
        #pragma unroll
        for (int mf = 0; mf < 4; mf++)
            #pragma unroll
            for (int nf = 0; nf < 8; nf++)
                mma16816(C[mf][nf], Ah[mf], &Bh[nf >> 1][(nf & 1) * 2]);
        uint32_t Al[4][4];
        #pragma unroll
        for (int mf = 0; mf < 4; mf++) ldsm4(Al[mf], st + A_LO + mf * 1280 + kk * 32 + a_off);
        #pragma unroll
        for (int mf = 0; mf < 4; mf++)
            #pragma unroll
            for (int nf = 0; nf < 8; nf++)
                mma16816(C[mf][nf], Al[mf], &Bh[nf >> 1][(nf & 1) * 2]);
    }
}

// ---------------- single merged prep kernel ----------------
__global__ void k_prep(const int* __restrict__ docs, const float* __restrict__ emb,
                       const float* __restrict__ wih_f, const float* __restrict__ wih_b,
                       const float* __restrict__ whh_f, const float* __restrict__ whh_b)
{
    int blk = blockIdx.x;
    if (blk < 4096) {                                  // init state
        int idx = blk * 256 + threadIdx.x;             // 1048576
        g_c[idx] = 0.f; g_pool[idx] = 0.f;
        g_h16[0][0][idx] = __float2half(0.f);
        g_h16[0][1][idx] = __float2half(0.f);
        if (idx < NS) {
            int cnt = 0;
            #pragma unroll
            for (int t = 0; t < SEQ; t++) cnt += (docs[idx * SEQ + t] != 0);
            g_len[idx] = cnt;
        }
    } else if (blk < 12096) {                          // embedding hi/lo split
        int idx = (blk - 4096) * 256 + threadIdx.x;    // 2048000
        float4 v = ((const float4*)emb)[idx];
        uint32_t h0, l0, h1, l1;
        split2(v.x, v.y, h0, l0); split2(v.z, v.w, h1, l1);
        ((uint2*)g_emb_h)[idx] = make_uint2(h0, h1);
        ((uint2*)g_emb_l)[idx] = make_uint2(l0, l1);
    } else if (blk < 13120) {                          // W_ih -> permuted fp16
        int idx = (blk - 12096) * 256 + threadIdx.x;   // 262144
        int k4 = idx & 63, p = (idx >> 6) & 2047, dir = idx >> 17;
        const float* W = dir ? wih_b : wih_f;
        float4 v = *(const float4*)(W + (size_t)((p & 3) * HDIM + (p >> 2)) * EDIM + k4 * 4);
        uint32_t h0 = pack_hi2(v.x, v.y), h1 = pack_hi2(v.z, v.w);
        *(uint2*)(g_wih_h + (size_t)(dir * GDIM + p) * EDIM + k4 * 4) = make_uint2(h0, h1);
    } else {                                           // W_hh -> permuted fp16
        int idx = (blk - 13120) * 256 + threadIdx.x;   // 524288
        int k4 = idx & 127, p = (idx >> 7) & 2047, dir = idx >> 18;
        const float* W = dir ? whh_b : whh_f;
        float4 v = *(const float4*)(W + (size_t)((p & 3) * HDIM + (p >> 2)) * HDIM + k4 * 4);
        uint32_t h0 = pack_hi2(v.x, v.y), h1 = pack_hi2(v.z, v.w);
        *(uint2*)(g_whh_h + (size_t)(dir * GDIM + p) * HDIM + k4 * 4) = make_uint2(h0, h1);
    }
}

// ---------------- fused recurrent step ----------------
// CTA: M=128 (n), N=256 (permuted gates p=4j+g), K=768 (512 h + 256 x); grid (8,8,2)
__global__ void __launch_bounds__(256, 1) k_step(
    const int* __restrict__ docs, const float* __restrict__ b_f,
    const float* __restrict__ b_b, int step)
{
    extern __shared__ char smem[];
    const uint32_t sb = smem_u32(smem);
    const int tid = threadIdx.x;
    const int dir = blockIdx.z;
    const int n0  = blockIdx.y * 128;
    const int p0  = blockIdx.x * 256;
    const int u   = dir ? (SEQ - 1 - step) : step;

    int*   tokS  = (int*)(smem + SM_TOK);
    float* biasS = (float*)(smem + SM_BIAS);
    int*   lenS  = (int*)(smem + SM_LEN);

    const __half* __restrict__ H0 = g_h16[step & 1][0] + (size_t)dir * NS * HDIM + (size_t)n0 * HDIM;
    const __half* __restrict__ H1 = g_h16[step & 1][1] + (size_t)dir * NS * HDIM + (size_t)n0 * HDIM;
    const __half* __restrict__ WHH = g_whh_h + (size_t)(dir * GDIM + p0) * HDIM;
    const __half* __restrict__ WIH = g_wih_h + (size_t)(dir * GDIM + p0) * EDIM;
    const float*  __restrict__ bias = dir ? b_b : b_f;

    float* __restrict__ gc = g_c    + (size_t)dir * NS * HDIM;
    float* __restrict__ gp = g_pool + (size_t)dir * NS * HDIM;
    const int j0 = p0 >> 2;

    if (tid < 128) {
        tokS[tid] = docs[(n0 + tid) * SEQ + u];
        lenS[tid] = g_len[n0 + tid];
    }
    { int p = p0 + tid; biasS[tid] = bias[(p & 3) * HDIM + (p >> 2)]; }
    __syncthreads();

    const int lane = tid & 31, w = tid >> 5;
    const int mw = w & 1, nw = w >> 1;
    const uint32_t a_off = (mw * 64 + (lane & 15)) * 80 + (lane >> 4) * 16;
    const uint32_t b_off = (nw * 64 + (lane & 7) + ((lane >> 4) << 3)) * 80 + ((lane >> 3) & 1) * 16;

    float bias0[8], bias1[8];
    const int qr = lane >> 2, c2 = (lane & 3) * 2, odd = lane & 1;
    #pragma unroll
    for (int nf = 0; nf < 8; nf++) {
        int pc = nw * 64 + nf * 8 + c2;
        bias0[nf] = biasS[pc];
        bias1[nf] = biasS[pc + 1];
    }

    float C[4][8][4];
    #pragma unroll
    for (int a = 0; a < 4; a++)
        #pragma unroll
        for (int b = 0; b < 8; b++)
            #pragma unroll
            for (int q = 0; q < 4; q++) C[a][b][q] = 0.f;

    auto fill = [&](int ch, uint32_t base) {
        if (ch < 16) {
            const int k0 = ch * 32;
            #pragma unroll
            for (int i = 0; i < 4; i++) {            // A: h hi/lo (2 planes)
                int s = tid + i * 256;
                int pl = s >> 9, rem = s & 511, r = rem >> 2, kc = rem & 3;
                const __half* src = (pl ? H1 : H0) + r * HDIM + k0 + kc * 8;
                CP_ASYNC16(base + pl * A_LO + r * 80 + kc * 16, src);
            }
            #pragma unroll
            for (int i = 0; i < 4; i++) {            // B: W_hh hi only
                int s = tid + i * 256;
                int row = s >> 2, kc = s & 3;
                CP_ASYNC16(base + B_HI + row * 80 + kc * 16,
                           WHH + (size_t)row * HDIM + k0 + kc * 8);
            }
        } else {
            const int k0 = (ch - 16) * 32;
            #pragma unroll
            for (int i = 0; i < 4; i++) {            // A: emb hi/lo gather
                int s = tid + i * 256;
                int pl = s >> 9, rem = s & 511, r = rem >> 2, kc = rem & 3;
                const __half* src = (pl ? g_emb_l : g_emb_h) + (size_t)tokS[r] * EDIM + k0 + kc * 8;
                CP_ASYNC16(base + pl * A_LO + r * 80 + kc * 16, src);
            }
            #pragma unroll
            for (int i = 0; i < 4; i++) {            // B: W_ih hi only
                int s = tid + i * 256;
                int row = s >> 2, kc = s & 3;
                CP_ASYNC16(base + B_HI + row * 80 + kc * 16,
                           WIH + (size_t)row * EDIM + k0 + kc * 8);
            }
        }
    };

    // prologue
    fill(0, sb);          CP_COMMIT();
    fill(1, sb + ST_SZ);  CP_COMMIT();

    // 4-stage, fill-before-wait, single barrier per chunk
    #pragma unroll 1
    for (int ch = 0; ch < NCH; ch++) {
        if (ch + 2 < NCH) {
            fill(ch + 2, sb + ((ch + 2) & 3) * ST_SZ);
            CP_COMMIT();
            CP_WAIT(2);
        } else if (ch == NCH - 1) {
            // prefetch c/pool into stages 0/1 (chunks 20/21: both already computed)
            #pragma unroll
            for (int i = 0; i < 8; i++) {
                int idx = tid + i * 256;
                int r = idx >> 4, q = idx & 15;
                CP_ASYNC16(sb + EP_C + r * 272 + q * 16, &gc[(size_t)(n0 + r) * HDIM + j0 + q * 4]);
                CP_ASYNC16(sb + EP_P + r * 272 + q * 16, &gp[(size_t)(n0 + r) * HDIM + j0 + q * 4]);
            }
            CP_COMMIT();
            CP_WAIT(0);
        } else {
            CP_WAIT(1);
        }
        __syncthreads();
        compute_chunk(C, sb + (ch & 3) * ST_SZ, a_off, b_off);
    }
    __syncthreads();    // all compute done before epilogue writes alias stage smem

    // ---------------- epilogue ----------------
    float*  cS  = (float*)(smem + EP_C);     // [128][68]
    float*  pS  = (float*)(smem + EP_P);     // [128][68]
    __half* hiS = (__half*)(smem + EP_HI);   // [128][72]
    __half* loS = (__half*)(smem + EP_LO);   // [128][72]

    #pragma unroll
    for (int mf = 0; mf < 4; mf++) {
        #pragma unroll
        for (int rh = 0; rh < 2; rh++) {
            const int rl = mw * 64 + mf * 16 + qr + rh * 8;
            const bool inlen = (u < lenS[rl]);
            #pragma unroll
            for (int nf = 0; nf < 8; nf++) {
                float y0 = C[mf][nf][rh * 2 + 0] + bias0[nf];
                float y1 = C[mf][nf][rh * 2 + 1] + bias1[nf];
                float o0 = __shfl_xor_sync(0xffffffffu, y0, 1);
                float o1 = __shfl_xor_sync(0xffffffffu, y1, 1);
                if (!odd) {
                    float si = 1.f / (1.f + __expf(-y0));
                    float sf = 1.f / (1.f + __expf(-y1));
                    float so = 1.f / (1.f + __expf(-o1));
                    float tg = __tanhf(o0);
                    int jl = (nw * 64 + nf * 8 + c2) >> 2;
                    float c = sf * cS[rl * 68 + jl] + si * tg;
                    float h = so * __tanhf(c);
                    cS[rl * 68 + jl] = c;
                    if (inlen) pS[rl * 68 + jl] += h;
                    __half hh = __float2half_rn(h);
                    hiS[rl * 72 + jl] = hh;
                    loS[rl * 72 + jl] = __float2half_rn(h - __half2float(hh));
                }
            }
        }
    }
    __syncthreads();

    __half* __restrict__ NH0 = g_h16[(step + 1) & 1][0] + (size_t)dir * NS * HDIM;
    __half* __restrict__ NH1 = g_h16[(step + 1) & 1][1] + (size_t)dir * NS * HDIM;
    #pragma unroll
    for (int i = 0; i < 8; i++) {
        int idx = tid + i * 256;
        int r = idx >> 4, q = idx & 15;
        *(float4*)&gc[(size_t)(n0 + r) * HDIM + j0 + q * 4] = *(float4*)&cS[r * 68 + q * 4];
        *(float4*)&gp[(size_t)(n0 + r) * HDIM + j0 + q * 4] = *(float4*)&pS[r * 68 + q * 4];
    }
    #pragma unroll
    for (int i = 0; i < 4; i++) {
        int idx = tid + i * 256;
        int r = idx >> 3, q = idx & 7;
        *(uint4*)&NH0[(size_t)(n0 + r) * HDIM + j0 + q * 8] = *(uint4*)&hiS[r * 72 + q * 8];
        *(uint4*)&NH1[(size_t)(n0 + r) * HDIM + j0 + q * 8] = *(uint4*)&loS[r * 72 + q * 8];
    }
}

// ---------------- final: pool/len, doc mask ----------------
__global__ void k_final(const int* __restrict__ doc_lens, float* __restrict__ out) {
    int idx = blockIdx.x * blockDim.x + threadIdx.x;  // 1048576
    int j  = idx & 1023;
    int nd = idx >> 10;
    int b = nd >> 5, d = nd & 31;
    float v = 0.f;
    if (d < doc_lens[b]) {
        int dirn = j >> 9;
        int jj   = j & 511;
        int len = g_len[nd];
        float denom = (float)(len > 0 ? len : 1);
        v = g_pool[dirn * NS * HDIM + nd * HDIM + jj] / denom;
    }
    out[idx] = v;
}

extern "C" void kernel_launch(void* const* d_in, const int* in_sizes, int n_in,
                              void* d_out, int out_size)
{
    const int* docs     = (const int*)d_in[0];
    const int* doc_lens = (const int*)d_in[1];
    int base = (n_in >= 10 && in_sizes[2] == 1) ? 3 : 2;
    const float* emb   = (const float*)d_in[base + 0];
    const float* wih_f = (const float*)d_in[base + 1];
    const float* whh_f = (const float*)d_in[base + 2];
    const float* b_f   = (const float*)d_in[base + 3];
    const float* wih_b = (const float*)d_in[base + 4];
    const float* whh_b = (const float*)d_in[base + 5];
    const float* b_b   = (const float*)d_in[base + 6];
    float* out = (float*)d_out;

    cudaFuncSetAttribute(k_step, cudaFuncAttributeMaxDynamicSharedMemorySize, SMEM_SZ);

    k_prep<<<15168, 256>>>(docs, emb, wih_f, wih_b, whh_f, whh_b);
    for (int t = 0; t < SEQ; t++)
        k_step<<<dim3(8, 8, 2), 256, SMEM_SZ>>>(docs, b_f, b_b, t);
    k_final<<<4096, 256>>>(doc_lens, out);
}

// round 7
// speedup vs baseline: 1.8301x; 1.4722x over previous
#include <cuda_runtime.h>
#include <cuda_fp16.h>
#include <cstdint>
#include <math.h>

#define NS   1024
#define SEQ  64
#define EDIM 256
#define HDIM 512
#define GDIM 2048
#define VOC  32000

// ---------------- device scratch ----------------
__device__ __half g_h16[2][2 * NS * HDIM];       // [parity][dir*NS*H + n*H + k], fp16 h
__device__ float  g_c   [2 * NS * HDIM];
__device__ float  g_pool[2 * NS * HDIM];
__device__ int    g_len [NS];
__device__ __half g_whh_h[2 * GDIM * HDIM];      // permuted fp16 weights
__device__ __half g_wih_h[2 * GDIM * EDIM];
__device__ __half g_emb_h[VOC * EDIM];           // fp16 embedding

// ---------------- helpers ----------------
__device__ __forceinline__ uint32_t smem_u32(const void* ptr) {
    uint32_t a;
    asm("{ .reg .u64 t; cvta.to.shared.u64 t, %1; cvt.u32.u64 %0, t; }" : "=r"(a) : "l"(ptr));
    return a;
}
#define CP_ASYNC16(dst, src) \
    asm volatile("cp.async.cg.shared.global [%0], [%1], 16;" :: "r"(dst), "l"(src) : "memory")
#define CP_COMMIT() asm volatile("cp.async.commit_group;" ::: "memory")
#define CP_WAIT(n)  asm volatile("cp.async.wait_group %0;" :: "n"(n) : "memory")

__device__ __forceinline__ void ldsm4(uint32_t* r, uint32_t addr) {
    asm volatile("ldmatrix.sync.aligned.m8n8.x4.shared.b16 {%0,%1,%2,%3}, [%4];"
        : "=r"(r[0]), "=r"(r[1]), "=r"(r[2]), "=r"(r[3]) : "r"(addr));
}
__device__ __forceinline__ void mma16816(float* c, const uint32_t* a, const uint32_t* b) {
    asm volatile("mma.sync.aligned.m16n8k16.row.col.f32.f16.f16.f32 "
        "{%0,%1,%2,%3}, {%4,%5,%6,%7}, {%8,%9}, {%0,%1,%2,%3};"
        : "+f"(c[0]), "+f"(c[1]), "+f"(c[2]), "+f"(c[3])
        : "r"(a[0]), "r"(a[1]), "r"(a[2]), "r"(a[3]), "r"(b[0]), "r"(b[1]));
}
__device__ __forceinline__ uint32_t pack_hi2(float a, float b) {
    __half2 H = __halves2half2(__float2half_rn(a), __float2half_rn(b));
    return *reinterpret_cast<uint32_t*>(&H);
}

// ---------------- smem layout ----------------
// stage: A 128x80 fp16 (10240) | B 256x80 fp16 (20480) = 30720; 4 stages
#define ST_SZ   30720
#define B_HI    10240
#define SM_TOK  122880
#define SM_BIAS 123392
#define SM_LEN  124416
#define SMEM_SZ 124928
#define NCH     24      // 16 h-chunks (K=512) + 8 x-chunks (K=256)
// epilogue staging (aliases dead stage smem):
#define EP_C    0       // float [128][68]  old->new c   (stages 0-1: dead at ch==23 prefetch)
#define EP_H    36864   // float [128][68]  fp32 h       (written after final barrier)
#define EP_P    73728   // float [128][68]  pool         (cp.async after final barrier; stages 2-3 dead)

// one K32 chunk: pure fp16 mma, warp tile 32x64
__device__ __forceinline__ void compute_chunk(float C[2][8][4], uint32_t st,
                                              uint32_t a_off, uint32_t b_off) {
    #pragma unroll
    for (int kk = 0; kk < 2; kk++) {
        uint32_t Ah[2][4], Bh[4][4];
        #pragma unroll
        for (int mf = 0; mf < 2; mf++) ldsm4(Ah[mf], st + mf * 1280 + kk * 32 + a_off);
        #pragma unroll
        for (int nq = 0; nq < 4; nq++) ldsm4(Bh[nq], st + B_HI + nq * 1280 + kk * 32 + b_off);
        #pragma unroll
        for (int mf = 0; mf < 2; mf++)
            #pragma unroll
            for (int nf = 0; nf < 8; nf++)
                mma16816(C[mf][nf], Ah[mf], &Bh[nf >> 1][(nf & 1) * 2]);
    }
}

// ---------------- single merged prep kernel ----------------
__global__ void k_prep(const int* __restrict__ docs, const float* __restrict__ emb,
                       const float* __restrict__ wih_f, const float* __restrict__ wih_b,
                       const float* __restrict__ whh_f, const float* __restrict__ whh_b)
{
    int blk = blockIdx.x;
    if (blk < 4096) {                                  // init state
        int idx = blk * 256 + threadIdx.x;             // 1048576
        g_c[idx] = 0.f; g_pool[idx] = 0.f;
        g_h16[0][idx] = __float2half(0.f);
        if (idx < NS) {
            int cnt = 0;
            #pragma unroll
            for (int t = 0; t < SEQ; t++) cnt += (docs[idx * SEQ + t] != 0);
            g_len[idx] = cnt;
        }
    } else if (blk < 12096) {                          // embedding -> fp16
        int idx = (blk - 4096) * 256 + threadIdx.x;    // 2048000
        float4 v = ((const float4*)emb)[idx];
        ((uint2*)g_emb_h)[idx] = make_uint2(pack_hi2(v.x, v.y), pack_hi2(v.z, v.w));
    } else if (blk < 13120) {                          // W_ih -> permuted fp16
        int idx = (blk - 12096) * 256 + threadIdx.x;   // 262144
        int k4 = idx & 63, p = (idx >> 6) & 2047, dir = idx >> 17;
        const float* W = dir ? wih_b : wih_f;
        float4 v = *(const float4*)(W + (size_t)((p & 3) * HDIM + (p >> 2)) * EDIM + k4 * 4);
        *(uint2*)(g_wih_h + (size_t)(dir * GDIM + p) * EDIM + k4 * 4) =
            make_uint2(pack_hi2(v.x, v.y), pack_hi2(v.z, v.w));
    } else {                                           // W_hh -> permuted fp16
        int idx = (blk - 13120) * 256 + threadIdx.x;   // 524288
        int k4 = idx & 127, p = (idx >> 7) & 2047, dir = idx >> 18;
        const float* W = dir ? whh_b : whh_f;
        float4 v = *(const float4*)(W + (size_t)((p & 3) * HDIM + (p >> 2)) * HDIM + k4 * 4);
        *(uint2*)(g_whh_h + (size_t)(dir * GDIM + p) * HDIM + k4 * 4) =
            make_uint2(pack_hi2(v.x, v.y), pack_hi2(v.z, v.w));
    }
}

// ---------------- fused recurrent step ----------------
// CTA: M=128 (n), N=256 (permuted gates p=4j+g), K=768; 512 threads, 16 warps (4m x 4n)
__global__ void __launch_bounds__(512, 1) k_step(
    const int* __restrict__ docs, const float* __restrict__ b_f,
    const float* __restrict__ b_b, int step)
{
    extern __shared__ char smem[];
    const uint32_t sb = smem_u32(smem);
    const int tid = threadIdx.x;
    const int dir = blockIdx.z;
    const int n0  = blockIdx.y * 128;
    const int p0  = blockIdx.x * 256;
    const int u   = dir ? (SEQ - 1 - step) : step;

    int*   tokS  = (int*)(smem + SM_TOK);
    float* biasS = (float*)(smem + SM_BIAS);
    int*   lenS  = (int*)(smem + SM_LEN);

    const __half* __restrict__ H0  = g_h16[step & 1] + (size_t)dir * NS * HDIM + (size_t)n0 * HDIM;
    const __half* __restrict__ WHH = g_whh_h + (size_t)(dir * GDIM + p0) * HDIM;
    const __half* __restrict__ WIH = g_wih_h + (size_t)(dir * GDIM + p0) * EDIM;
    const float*  __restrict__ bias = dir ? b_b : b_f;

    float* __restrict__ gc = g_c    + (size_t)dir * NS * HDIM;
    float* __restrict__ gp = g_pool + (size_t)dir * NS * HDIM;
    const int j0 = p0 >> 2;

    if (tid < 128) {
        tokS[tid] = docs[(n0 + tid) * SEQ + u];
        lenS[tid] = g_len[n0 + tid];
    }
    if (tid < 256) { int p = p0 + tid; biasS[tid] = bias[(p & 3) * HDIM + (p >> 2)]; }
    __syncthreads();

    const int lane = tid & 31, w = tid >> 5;
    const int mw = w & 3, nw = w >> 2;
    const uint32_t a_off = (mw * 32 + (lane & 15)) * 80 + (lane >> 4) * 16;
    const uint32_t b_off = (nw * 64 + (lane & 7) + ((lane >> 4) << 3)) * 80 + ((lane >> 3) & 1) * 16;

    float bias0[8], bias1[8];
    const int qr = lane >> 2, c2 = (lane & 3) * 2, odd = lane & 1;
    #pragma unroll
    for (int nf = 0; nf < 8; nf++) {
        int pc = nw * 64 + nf * 8 + c2;
        bias0[nf] = biasS[pc];
        bias1[nf] = biasS[pc + 1];
    }

    float C[2][8][4];
    #pragma unroll
    for (int a = 0; a < 2; a++)
        #pragma unroll
        for (int b = 0; b < 8; b++)
            #pragma unroll
            for (int q = 0; q < 4; q++) C[a][b][q] = 0.f;

    auto fill = [&](int ch, uint32_t base) {
        if (ch < 16) {
            const int k0 = ch * 32;
            {   // A: h fp16, 512 slots of 16B, 1/thread
                int r = tid >> 2, kc = tid & 3;
                CP_ASYNC16(base + r * 80 + kc * 16, H0 + r * HDIM + k0 + kc * 8);
            }
            #pragma unroll
            for (int i = 0; i < 2; i++) {            // B: W_hh, 1024 slots
                int s = tid + i * 512;
                int row = s >> 2, kc = s & 3;
                CP_ASYNC16(base + B_HI + row * 80 + kc * 16,
                           WHH + (size_t)row * HDIM + k0 + kc * 8);
            }
        } else {
            const int k0 = (ch - 16) * 32;
            {   // A: emb gather fp16
                int r = tid >> 2, kc = tid & 3;
                CP_ASYNC16(base + r * 80 + kc * 16,
                           g_emb_h + (size_t)tokS[r] * EDIM + k0 + kc * 8);
            }
            #pragma unroll
            for (int i = 0; i < 2; i++) {            // B: W_ih
                int s = tid + i * 512;
                int row = s >> 2, kc = s & 3;
                CP_ASYNC16(base + B_HI + row * 80 + kc * 16,
                           WIH + (size_t)row * EDIM + k0 + kc * 8);
            }
        }
    };

    // prologue
    fill(0, sb);          CP_COMMIT();
    fill(1, sb + ST_SZ);  CP_COMMIT();

    // 4-stage, fill-before-wait, single barrier per chunk
    #pragma unroll 1
    for (int ch = 0; ch < NCH; ch++) {
        if (ch + 2 < NCH) {
            fill(ch + 2, sb + ((ch + 2) & 3) * ST_SZ);
            CP_COMMIT();
            CP_WAIT(2);
        } else if (ch == NCH - 1) {
            // prefetch old c into EP_C (stages 0-1: last used ch 20/21, all threads past ch22 barrier)
            #pragma unroll
            for (int i = 0; i < 4; i++) {
                int idx = tid + i * 512;             // 2048 slots
                int r = idx >> 4, q = idx & 15;
                CP_ASYNC16(sb + EP_C + r * 272 + q * 16, &gc[(size_t)(n0 + r) * HDIM + j0 + q * 4]);
            }
            CP_COMMIT();
            CP_WAIT(0);
        } else {
            CP_WAIT(1);
        }
        __syncthreads();
        compute_chunk(C, sb + (ch & 3) * ST_SZ, a_off, b_off);
    }
    __syncthreads();     // all compute done; all stages dead

    // pool prefetch into EP_P (overlaps phase-A gate math)
    #pragma unroll
    for (int i = 0; i < 4; i++) {
        int idx = tid + i * 512;
        int r = idx >> 4, q = idx & 15;
        CP_ASYNC16(sb + EP_P + r * 272 + q * 16, &gp[(size_t)(n0 + r) * HDIM + j0 + q * 4]);
    }
    CP_COMMIT();

    // ---------------- epilogue phase A: gates -> c (in place), h fp32 ----------------
    float* cS = (float*)(smem + EP_C);    // [128][68]
    float* hS = (float*)(smem + EP_H);    // [128][68]
    float* pS = (float*)(smem + EP_P);    // [128][68]

    #pragma unroll
    for (int mf = 0; mf < 2; mf++) {
        #pragma unroll
        for (int rh = 0; rh < 2; rh++) {
            const int rl = mw * 32 + mf * 16 + qr + rh * 8;
            #pragma unroll
            for (int nf = 0; nf < 8; nf++) {
                float y0 = C[mf][nf][rh * 2 + 0] + bias0[nf];
                float y1 = C[mf][nf][rh * 2 + 1] + bias1[nf];
                float o0 = __shfl_xor_sync(0xffffffffu, y0, 1);
                float o1 = __shfl_xor_sync(0xffffffffu, y1, 1);
                if (!odd) {
                    float si = 1.f / (1.f + __expf(-y0));
                    float sf = 1.f / (1.f + __expf(-y1));
                    float so = 1.f / (1.f + __expf(-o1));
                    float tg = __tanhf(o0);
                    int jl = (nw * 64 + nf * 8 + c2) >> 2;
                    float c = sf * cS[rl * 68 + jl] + si * tg;
                    float h = so * __tanhf(c);
                    cS[rl * 68 + jl] = c;
                    hS[rl * 68 + jl] = h;
                }
            }
        }
    }
    CP_WAIT(0);
    __syncthreads();

    // ---------------- epilogue phase B: coalesced pool/c/h stores ----------------
    __half* __restrict__ NH = g_h16[(step + 1) & 1] + (size_t)dir * NS * HDIM;
    #pragma unroll
    for (int i = 0; i < 4; i++) {
        int idx = tid + i * 512;
        int r = idx >> 4, q = idx & 15;
        size_t go = (size_t)(n0 + r) * HDIM + j0 + q * 4;
        float4 cv = *(float4*)&cS[r * 68 + q * 4];
        float4 hv = *(float4*)&hS[r * 68 + q * 4];
        *(float4*)&gc[go] = cv;
        if (u < lenS[r]) {
            float4 pv = *(float4*)&pS[r * 68 + q * 4];
            pv.x += hv.x; pv.y += hv.y; pv.z += hv.z; pv.w += hv.w;
            *(float4*)&gp[go] = pv;
        }
        uint2 hp = make_uint2(pack_hi2(hv.x, hv.y), pack_hi2(hv.z, hv.w));
        *(uint2*)&NH[go] = hp;
    }
}

// ---------------- final: pool/len, doc mask ----------------
__global__ void k_final(const int* __restrict__ doc_lens, float* __restrict__ out) {
    int idx = blockIdx.x * blockDim.x + threadIdx.x;  // 1048576
    int j  = idx & 1023;
    int nd = idx >> 10;
    int b = nd >> 5, d = nd & 31;
    float v = 0.f;
    if (d < doc_lens[b]) {
        int dirn = j >> 9;
        int jj   = j & 511;
        int len = g_len[nd];
        float denom = (float)(len > 0 ? len : 1);
        v = g_pool[dirn * NS * HDIM + nd * HDIM + jj] / denom;
    }
    out[idx] = v;
}

extern "C" void kernel_launch(void* const* d_in, const int* in_sizes, int n_in,
                              void* d_out, int out_size)
{
    const int* docs     = (const int*)d_in[0];
    const int* doc_lens = (const int*)d_in[1];
    int base = (n_in >= 10 && in_sizes[2] == 1) ? 3 : 2;
    const float* emb   = (const float*)d_in[base + 0];
    const float* wih_f = (const float*)d_in[base + 1];
    const float* whh_f = (const float*)d_in[base + 2];
    const float* b_f   = (const float*)d_in[base + 3];
    const float* wih_b = (const float*)d_in[base + 4];
    const float* whh_b = (const float*)d_in[base + 5];
    const float* b_b   = (const float*)d_in[base + 6];
    float* out = (float*)d_out;

    cudaFuncSetAttribute(k_step, cudaFuncAttributeMaxDynamicSharedMemorySize, SMEM_SZ);

    k_prep<<<15168, 256>>>(docs, emb, wih_f, wih_b, whh_f, whh_b);
    for (int t = 0; t < SEQ; t++)
        k_step<<<dim3(8, 8, 2), 512, SMEM_SZ>>>(docs, b_f, b_b, t);
    k_final<<<4096, 256>>>(doc_lens, out);
}

// round 8
// speedup vs baseline: 1.9287x; 1.0539x over previous
#include <cuda_runtime.h>
#include <cuda_fp16.h>
#include <cstdint>
#include <math.h>

#define NS   1024
#define SEQ  64
#define EDIM 256
#define HDIM 512
#define GDIM 2048
#define VOC  32000

// ---------------- device scratch ----------------
__device__ __half   g_h16[2][2 * NS * HDIM];     // [parity][dir*NS*H + n*H + k]
__device__ int      g_len [NS];
__device__ __half   g_whh_h[2 * GDIM * HDIM];    // permuted fp16 weights
__device__ __half   g_wih_h[2 * GDIM * EDIM];
__device__ __half   g_emb_h[VOC * EDIM];         // fp16 embedding
__device__ unsigned g_sync;

// ---------------- helpers ----------------
__device__ __forceinline__ uint32_t smem_u32(const void* ptr) {
    uint32_t a;
    asm("{ .reg .u64 t; cvta.to.shared.u64 t, %1; cvt.u32.u64 %0, t; }" : "=r"(a) : "l"(ptr));
    return a;
}
#define CP_ASYNC16(dst, src) \
    asm volatile("cp.async.cg.shared.global [%0], [%1], 16;" :: "r"(dst), "l"(src) : "memory")
#define CP_COMMIT() asm volatile("cp.async.commit_group;" ::: "memory")
#define CP_WAIT(n)  asm volatile("cp.async.wait_group %0;" :: "n"(n) : "memory")

__device__ __forceinline__ void ldsm4(uint32_t* r, uint32_t addr) {
    asm volatile("ldmatrix.sync.aligned.m8n8.x4.shared.b16 {%0,%1,%2,%3}, [%4];"
        : "=r"(r[0]), "=r"(r[1]), "=r"(r[2]), "=r"(r[3]) : "r"(addr));
}
__device__ __forceinline__ void mma16816(float* c, const uint32_t* a, const uint32_t* b) {
    asm volatile("mma.sync.aligned.m16n8k16.row.col.f32.f16.f16.f32 "
        "{%0,%1,%2,%3}, {%4,%5,%6,%7}, {%8,%9}, {%0,%1,%2,%3};"
        : "+f"(c[0]), "+f"(c[1]), "+f"(c[2]), "+f"(c[3])
        : "r"(a[0]), "r"(a[1]), "r"(a[2]), "r"(a[3]), "r"(b[0]), "r"(b[1]));
}
__device__ __forceinline__ uint32_t pack_hi2(float a, float b) {
    __half2 H = __halves2half2(__float2half_rn(a), __float2half_rn(b));
    return *reinterpret_cast<uint32_t*>(&H);
}

// ---------------- smem layout (bytes) ----------------
// 5 pipeline stages, each: A 128x80 fp16 (10240) | B 256x80 fp16 (20480)
#define ST_SZ   30720
#define B_HI    10240
#define NSTG    5
#define SM_C    153600              // float [128][68]   persistent c
#define SM_P    188416              // float [128][68]   persistent pool
#define SM_TOK  223232              // int   [128]
#define SM_BIAS 223744              // float [256]
#define SM_LEN  224768              // int   [128]
#define SMEM_SZ 225280
#define SM_HS   0                   // float [128][68] h staging, aliases stages 0-1 (dead in epilogue)
#define NCH     24                  // 16 h-chunks (K=512) + 8 x-chunks (K=256)

// one K32 chunk: fp16 mma, warp tile 32x64
__device__ __forceinline__ void compute_chunk(float C[2][8][4], uint32_t st,
                                              uint32_t a_off, uint32_t b_off) {
    #pragma unroll
    for (int kk = 0; kk < 2; kk++) {
        uint32_t Ah[2][4], Bh[4][4];
        #pragma unroll
        for (int mf = 0; mf < 2; mf++) ldsm4(Ah[mf], st + mf * 1280 + kk * 32 + a_off);
        #pragma unroll
        for (int nq = 0; nq < 4; nq++) ldsm4(Bh[nq], st + B_HI + nq * 1280 + kk * 32 + b_off);
        #pragma unroll
        for (int mf = 0; mf < 2; mf++)
            #pragma unroll
            for (int nf = 0; nf < 8; nf++)
                mma16816(C[mf][nf], Ah[mf], &Bh[nf >> 1][(nf & 1) * 2]);
    }
}

// ---------------- merged prep ----------------
__global__ void k_prep(const int* __restrict__ docs, const float* __restrict__ emb,
                       const float* __restrict__ wih_f, const float* __restrict__ wih_b,
                       const float* __restrict__ whh_f, const float* __restrict__ whh_b)
{
    int blk = blockIdx.x;
    if (blk < 4096) {                                  // zero h parity0, lengths, sync counter
        int idx = blk * 256 + threadIdx.x;             // 1048576
        g_h16[0][idx] = __float2half(0.f);
        if (idx < NS) {
            int cnt = 0;
            #pragma unroll
            for (int t = 0; t < SEQ; t++) cnt += (docs[idx * SEQ + t] != 0);
            g_len[idx] = cnt;
        }
        if (idx == 0) g_sync = 0u;
    } else if (blk < 12096) {                          // embedding -> fp16
        int idx = (blk - 4096) * 256 + threadIdx.x;    // 2048000
        float4 v = ((const float4*)emb)[idx];
        ((uint2*)g_emb_h)[idx] = make_uint2(pack_hi2(v.x, v.y), pack_hi2(v.z, v.w));
    } else if (blk < 13120) {                          // W_ih -> permuted fp16
        int idx = (blk - 12096) * 256 + threadIdx.x;   // 262144
        int k4 = idx & 63, p = (idx >> 6) & 2047, dir = idx >> 17;
        const float* W = dir ? wih_b : wih_f;
        float4 v = *(const float4*)(W + (size_t)((p & 3) * HDIM + (p >> 2)) * EDIM + k4 * 4);
        *(uint2*)(g_wih_h + (size_t)(dir * GDIM + p) * EDIM + k4 * 4) =
            make_uint2(pack_hi2(v.x, v.y), pack_hi2(v.z, v.w));
    } else {                                           // W_hh -> permuted fp16
        int idx = (blk - 13120) * 256 + threadIdx.x;   // 524288
        int k4 = idx & 127, p = (idx >> 7) & 2047, dir = idx >> 18;
        const float* W = dir ? whh_b : whh_f;
        float4 v = *(const float4*)(W + (size_t)((p & 3) * HDIM + (p >> 2)) * HDIM + k4 * 4);
        *(uint2*)(g_whh_h + (size_t)(dir * GDIM + p) * HDIM + k4 * 4) =
            make_uint2(pack_hi2(v.x, v.y), pack_hi2(v.z, v.w));
    }
}

// ---------------- persistent step kernel: all 64 timesteps ----------------
// grid (8,8,2) = 128 CTAs (1/SM, co-resident). CTA: M=128 (n), N=256 (gates p=4j+g), K=768.
__global__ void __launch_bounds__(512, 1) k_persist(
    const int* __restrict__ docs, const int* __restrict__ doc_lens,
    const float* __restrict__ b_f, const float* __restrict__ b_b,
    float* __restrict__ out)
{
    extern __shared__ char smem[];
    const uint32_t sb = smem_u32(smem);
    const int tid = threadIdx.x;
    const int dir = blockIdx.z;
    const int n0  = blockIdx.y * 128;
    const int p0  = blockIdx.x * 256;

    int*   tokS  = (int*)(smem + SM_TOK);
    float* biasS = (float*)(smem + SM_BIAS);
    int*   lenS  = (int*)(smem + SM_LEN);
    float* cS    = (float*)(smem + SM_C);   // [128][68]
    float* pS    = (float*)(smem + SM_P);   // [128][68]
    float* hS    = (float*)(smem + SM_HS);  // [128][68] (aliases stage smem)

    const __half* __restrict__ WHH = g_whh_h + (size_t)(dir * GDIM + p0) * HDIM;
    const __half* __restrict__ WIH = g_wih_h + (size_t)(dir * GDIM + p0) * EDIM;
    const float*  __restrict__ bias = dir ? b_b : b_f;
    const int j0 = p0 >> 2;

    // one-time init
    if (tid < 128) lenS[tid] = g_len[n0 + tid];
    if (tid < 256) { int p = p0 + tid; biasS[tid] = bias[(p & 3) * HDIM + (p >> 2)]; }
    #pragma unroll
    for (int i = tid; i < 2 * 128 * 68; i += 512) cS[i] = 0.f;   // zeros cS and pS (contiguous)

    const int lane = tid & 31, w = tid >> 5;
    const int mw = w & 3, nw = w >> 2;
    const uint32_t a_off = (mw * 32 + (lane & 15)) * 80 + (lane >> 4) * 16;
    const uint32_t b_off = (nw * 64 + (lane & 7) + ((lane >> 4) << 3)) * 80 + ((lane >> 3) & 1) * 16;
    const int qr = lane >> 2, c2 = (lane & 3) * 2, odd = lane & 1;

    __syncthreads();
    float bias0[8], bias1[8];
    #pragma unroll
    for (int nf = 0; nf < 8; nf++) {
        int pc = nw * 64 + nf * 8 + c2;
        bias0[nf] = biasS[pc];
        bias1[nf] = biasS[pc + 1];
    }

    #pragma unroll 1
    for (int step = 0; step < SEQ; step++) {
        const int u = dir ? (SEQ - 1 - step) : step;
        const __half* __restrict__ H0 = g_h16[step & 1] + (size_t)dir * NS * HDIM + (size_t)n0 * HDIM;

        if (tid < 128) tokS[tid] = docs[(n0 + tid) * SEQ + u];
        __syncthreads();

        auto fill = [&](int ch) {
            uint32_t base = sb + (uint32_t)(ch % NSTG) * ST_SZ;
            if (ch < 16) {
                const int k0 = ch * 32;
                {   int r = tid >> 2, kc = tid & 3;
                    CP_ASYNC16(base + r * 80 + kc * 16, H0 + r * HDIM + k0 + kc * 8); }
                #pragma unroll
                for (int i = 0; i < 2; i++) {
                    int s = tid + i * 512;
                    int row = s >> 2, kc = s & 3;
                    CP_ASYNC16(base + B_HI + row * 80 + kc * 16,
                               WHH + (size_t)row * HDIM + k0 + kc * 8);
                }
            } else {
                const int k0 = (ch - 16) * 32;
                {   int r = tid >> 2, kc = tid & 3;
                    CP_ASYNC16(base + r * 80 + kc * 16,
                               g_emb_h + (size_t)tokS[r] * EDIM + k0 + kc * 8); }
                #pragma unroll
                for (int i = 0; i < 2; i++) {
                    int s = tid + i * 512;
                    int row = s >> 2, kc = s & 3;
                    CP_ASYNC16(base + B_HI + row * 80 + kc * 16,
                               WIH + (size_t)row * EDIM + k0 + kc * 8);
                }
            }
        };

        float C[2][8][4];
        #pragma unroll
        for (int a = 0; a < 2; a++)
            #pragma unroll
            for (int b = 0; b < 8; b++)
                #pragma unroll
                for (int q = 0; q < 4; q++) C[a][b][q] = 0.f;

        fill(0); CP_COMMIT();
        fill(1); CP_COMMIT();
        fill(2); CP_COMMIT();

        #pragma unroll 1
        for (int ch = 0; ch < NCH; ch++) {
            if (ch + 3 < NCH)      { fill(ch + 3); CP_COMMIT(); CP_WAIT(3); }
            else if (ch + 2 < NCH) { CP_WAIT(2); }
            else if (ch + 1 < NCH) { CP_WAIT(1); }
            else                   { CP_WAIT(0); }
            __syncthreads();
            compute_chunk(C, sb + (uint32_t)(ch % NSTG) * ST_SZ, a_off, b_off);
        }
        __syncthreads();   // stages dead; hS may be written

        // ---- epilogue phase A: gates -> c (smem), pool (smem), h -> hS ----
        #pragma unroll
        for (int mf = 0; mf < 2; mf++) {
            #pragma unroll
            for (int rh = 0; rh < 2; rh++) {
                const int rl = mw * 32 + mf * 16 + qr + rh * 8;
                const bool inlen = (u < lenS[rl]);
                #pragma unroll
                for (int nf = 0; nf < 8; nf++) {
                    float y0 = C[mf][nf][rh * 2 + 0] + bias0[nf];
                    float y1 = C[mf][nf][rh * 2 + 1] + bias1[nf];
                    float o0 = __shfl_xor_sync(0xffffffffu, y0, 1);
                    float o1 = __shfl_xor_sync(0xffffffffu, y1, 1);
                    if (!odd) {
                        float si = 1.f / (1.f + __expf(-y0));
                        float sf = 1.f / (1.f + __expf(-y1));
                        float so = 1.f / (1.f + __expf(-o1));
                        float tg = __tanhf(o0);
                        int jl = (nw * 64 + nf * 8 + c2) >> 2;
                        float c = sf * cS[rl * 68 + jl] + si * tg;
                        float h = so * __tanhf(c);
                        cS[rl * 68 + jl] = c;
                        if (inlen) pS[rl * 68 + jl] += h;
                        hS[rl * 68 + jl] = h;
                    }
                }
            }
        }
        __syncthreads();

        // ---- epilogue phase B: coalesced fp16 h store ----
        __half* __restrict__ NH = g_h16[(step + 1) & 1] + (size_t)dir * NS * HDIM;
        #pragma unroll
        for (int i = 0; i < 4; i++) {
            int idx = tid + i * 512;
            int r = idx >> 4, q = idx & 15;
            float4 hv = *(float4*)&hS[r * 68 + q * 4];
            *(uint2*)&NH[(size_t)(n0 + r) * HDIM + j0 + q * 4] =
                make_uint2(pack_hi2(hv.x, hv.y), pack_hi2(hv.z, hv.w));
        }

        // ---- grid sync (release h writes; acquire all CTAs' h) ----
        __syncthreads();
        if (tid == 0) {
            __threadfence();
            atomicAdd(&g_sync, 1u);
            unsigned target = 128u * (unsigned)(step + 1);
            while (*(volatile unsigned*)&g_sync < target) __nanosleep(64);
            __threadfence();
        }
        __syncthreads();
    }

    // ---- final: pool/len, doc mask, write out slice ----
    #pragma unroll 1
    for (int i = tid; i < 128 * 16; i += 512) {
        int r = i >> 4, q = i & 15;
        int nd = n0 + r;
        int b = nd >> 5, d = nd & 31;
        float4 v = make_float4(0.f, 0.f, 0.f, 0.f);
        if (d < doc_lens[b]) {
            int len = lenS[r];
            float inv = 1.f / (float)(len > 0 ? len : 1);
            float4 pv = *(float4*)&pS[r * 68 + q * 4];
            v = make_float4(pv.x * inv, pv.y * inv, pv.z * inv, pv.w * inv);
        }
        *(float4*)&out[(size_t)nd * 1024 + dir * 512 + j0 + q * 4] = v;
    }
}

extern "C" void kernel_launch(void* const* d_in, const int* in_sizes, int n_in,
                              void* d_out, int out_size)
{
    const int* docs     = (const int*)d_in[0];
    const int* doc_lens = (const int*)d_in[1];
    int base = (n_in >= 10 && in_sizes[2] == 1) ? 3 : 2;
    const float* emb   = (const float*)d_in[base + 0];
    const float* wih_f = (const float*)d_in[base + 1];
    const float* whh_f = (const float*)d_in[base + 2];
    const float* b_f   = (const float*)d_in[base + 3];
    const float* wih_b = (const float*)d_in[base + 4];
    const float* whh_b = (const float*)d_in[base + 5];
    const float* b_b   = (const float*)d_in[base + 6];
    float* out = (float*)d_out;

    cudaFuncSetAttribute(k_persist, cudaFuncAttributeMaxDynamicSharedMemorySize, SMEM_SZ);

    k_prep   <<<15168, 256>>>(docs, emb, wih_f, wih_b, whh_f, whh_b);
    k_persist<<<dim3(8, 8, 2), 512, SMEM_SZ>>>(docs, doc_lens, b_f, b_b, out);
}

// round 10
// speedup vs baseline: 2.4873x; 1.2897x over previous
#include <cuda_runtime.h>
#include <cuda_fp16.h>
#include <cstdint>
#include <math.h>

#define NS   1024
#define SEQ  64
#define EDIM 256
#define HDIM 512
#define GDIM 2048
#define VOC  32000

// ---------------- device scratch ----------------
__device__ __half   g_h16[2][2 * NS * HDIM];     // [parity][dir*NS*H + n*H + k]
__device__ int      g_len [NS];
__device__ __half   g_whh_h[2 * GDIM * HDIM];    // permuted fp16 weights
__device__ __half   g_wih_h[2 * GDIM * EDIM];
__device__ __half   g_emb_h[VOC * EDIM];         // fp16 embedding
__device__ unsigned g_sync;

// ---------------- helpers ----------------
__device__ __forceinline__ uint32_t smem_u32(const void* ptr) {
    uint32_t a;
    asm("{ .reg .u64 t; cvta.to.shared.u64 t, %1; cvt.u32.u64 %0, t; }" : "=r"(a) : "l"(ptr));
    return a;
}
#define CP_ASYNC16(dst, src) \
    asm volatile("cp.async.cg.shared.global [%0], [%1], 16;" :: "r"(dst), "l"(src) : "memory")
#define CP_COMMIT() asm volatile("cp.async.commit_group;" ::: "memory")
#define CP_WAIT(n)  asm volatile("cp.async.wait_group %0;" :: "n"(n) : "memory")

__device__ __forceinline__ void ldsm4(uint32_t* r, uint32_t addr) {
    asm volatile("ldmatrix.sync.aligned.m8n8.x4.shared.b16 {%0,%1,%2,%3}, [%4];"
        : "=r"(r[0]), "=r"(r[1]), "=r"(r[2]), "=r"(r[3]) : "r"(addr));
}
__device__ __forceinline__ void mma16816(float* c, const uint32_t* a, const uint32_t* b) {
    asm volatile("mma.sync.aligned.m16n8k16.row.col.f32.f16.f16.f32 "
        "{%0,%1,%2,%3}, {%4,%5,%6,%7}, {%8,%9}, {%0,%1,%2,%3};"
        : "+f"(c[0]), "+f"(c[1]), "+f"(c[2]), "+f"(c[3])
        : "r"(a[0]), "r"(a[1]), "r"(a[2]), "r"(a[3]), "r"(b[0]), "r"(b[1]));
}
__device__ __forceinline__ uint32_t pack_hi2(float a, float b) {
    __half2 H = __halves2half2(__float2half_rn(a), __float2half_rn(b));
    return *reinterpret_cast<uint32_t*>(&H);
}

// ---------------- smem layout (bytes) ----------------
// stage: A 128x64B swizzled (8192) | B 256x64B swizzled (16384) = 24576; 6 stages
#define ST_SZ   24576
#define B_OFF   8192
#define NSTG    6
#define SM_C    147456              // float [128][68]  persistent c
#define SM_P    182272              // float [128][68]  persistent pool
#define SM_TOK  217088              // int   [2][128]   double-buffered tokens
#define SM_BIAS 218112              // float [256]
#define SM_LEN  219136              // int   [128]
#define SMEM_SZ 219648
#define SM_HS   0                   // float [128][68] h staging (aliases stages 0-1, dead in epilogue)
#define NCH     24                  // ch 0-7: x (W_ih+emb), ch 8-23: h (W_hh+h)

// ---------------- merged prep ----------------
__global__ void k_prep(const int* __restrict__ docs, const float* __restrict__ emb,
                       const float* __restrict__ wih_f, const float* __restrict__ wih_b,
                       const float* __restrict__ whh_f, const float* __restrict__ whh_b)
{
    int blk = blockIdx.x;
    if (blk < 4096) {
        int idx = blk * 256 + threadIdx.x;             // 1048576
        g_h16[0][idx] = __float2half(0.f);
        if (idx < NS) {
            int cnt = 0;
            #pragma unroll
            for (int t = 0; t < SEQ; t++) cnt += (docs[idx * SEQ + t] != 0);
            g_len[idx] = cnt;
        }
        if (idx == 0) g_sync = 0u;
    } else if (blk < 12096) {
        int idx = (blk - 4096) * 256 + threadIdx.x;    // 2048000
        float4 v = ((const float4*)emb)[idx];
        ((uint2*)g_emb_h)[idx] = make_uint2(pack_hi2(v.x, v.y), pack_hi2(v.z, v.w));
    } else if (blk < 13120) {
        int idx = (blk - 12096) * 256 + threadIdx.x;   // 262144
        int k4 = idx & 63, p = (idx >> 6) & 2047, dir = idx >> 17;
        const float* W = dir ? wih_b : wih_f;
        float4 v = *(const float4*)(W + (size_t)((p & 3) * HDIM + (p >> 2)) * EDIM + k4 * 4);
        *(uint2*)(g_wih_h + (size_t)(dir * GDIM + p) * EDIM + k4 * 4) =
            make_uint2(pack_hi2(v.x, v.y), pack_hi2(v.z, v.w));
    } else {
        int idx = (blk - 13120) * 256 + threadIdx.x;   // 524288
        int k4 = idx & 127, p = (idx >> 7) & 2047, dir = idx >> 18;
        const float* W = dir ? whh_b : whh_f;
        float4 v = *(const float4*)(W + (size_t)((p & 3) * HDIM + (p >> 2)) * HDIM + k4 * 4);
        *(uint2*)(g_whh_h + (size_t)(dir * GDIM + p) * HDIM + k4 * 4) =
            make_uint2(pack_hi2(v.x, v.y), pack_hi2(v.z, v.w));
    }
}

// ---------------- persistent step kernel ----------------
// grid (8,8,2) = 128 CTAs (1/SM). CTA: M=128 (n), N=256 (gates p=4j+g), K=768.
__global__ void __launch_bounds__(512, 1) k_persist(
    const int* __restrict__ docs, const int* __restrict__ doc_lens,
    const float* __restrict__ b_f, const float* __restrict__ b_b,
    float* __restrict__ out)
{
    extern __shared__ char smem[];
    const uint32_t sb = smem_u32(smem);
    const int tid = threadIdx.x;
    const int dir = blockIdx.z;
    const int n0  = blockIdx.y * 128;
    const int p0  = blockIdx.x * 256;

    int*   tokS  = (int*)(smem + SM_TOK);    // [2][128]
    float* biasS = (float*)(smem + SM_BIAS);
    int*   lenS  = (int*)(smem + SM_LEN);
    float* cS    = (float*)(smem + SM_C);
    float* pS    = (float*)(smem + SM_P);
    float* hS    = (float*)(smem + SM_HS);

    const __half* __restrict__ WHH = g_whh_h + (size_t)(dir * GDIM + p0) * HDIM;
    const __half* __restrict__ WIH = g_wih_h + (size_t)(dir * GDIM + p0) * EDIM;
    const float*  __restrict__ bias = dir ? b_b : b_f;
    const int j0 = p0 >> 2;

    if (tid < 128) lenS[tid] = g_len[n0 + tid];
    if (tid < 256) { int p = p0 + tid; biasS[tid] = bias[(p & 3) * HDIM + (p >> 2)]; }
    #pragma unroll
    for (int i = tid; i < 2 * 128 * 68; i += 512) cS[i] = 0.f;   // zeros cS + pS (contiguous)

    const int lane = tid & 31, w = tid >> 5;
    const int mw = w & 3, nw = w >> 2;
    // swizzled ldsm addressing (64B rows, kc ^= (row>>1)&3)
    const uint32_t aBase = (uint32_t)(mw * 32 + (lane & 15)) * 64;
    const uint32_t aX    = ((lane & 15) >> 1) & 3;
    const uint32_t axk0  = (((lane >> 4) ^ aX) << 4);
    const uint32_t axk1  = (((2 + (lane >> 4)) ^ aX) << 4);
    const uint32_t bBase = B_OFF + (uint32_t)(nw * 64 + (lane & 7) + ((lane >> 4) << 3)) * 64;
    const uint32_t bX    = ((lane & 7) >> 1) & 3;
    const uint32_t bxk0  = ((((lane >> 3) & 1) ^ bX) << 4);
    const uint32_t bxk1  = (((2 + ((lane >> 3) & 1)) ^ bX) << 4);
    const int qr = lane >> 2, c2 = (lane & 3) * 2, odd = lane & 1;

    __syncthreads();
    float bias0[8], bias1[8];
    #pragma unroll
    for (int nf = 0; nf < 8; nf++) {
        int pc = nw * 64 + nf * 8 + c2;
        bias0[nf] = biasS[pc];
        bias1[nf] = biasS[pc + 1];
    }

    float C[2][8][4];

    // fill one K32 chunk; ch<8 = x (emb gather + W_ih), ch>=8 = h (h + W_hh)
    auto fill_chunk = [&](int ch, const int* tok, const __half* Hc) {
        uint32_t base = sb + (uint32_t)(ch % NSTG) * ST_SZ;
        if (ch < 8) {
            const int k0 = ch * 32;
            {   int r = tid >> 2, kc = tid & 3;
                uint32_t d = base + r * 64 + (((kc ^ ((r >> 1) & 3))) << 4);
                CP_ASYNC16(d, g_emb_h + (size_t)tok[r] * EDIM + k0 + kc * 8); }
            #pragma unroll
            for (int i = 0; i < 2; i++) {
                int s = tid + i * 512;
                int row = s >> 2, kc = s & 3;
                uint32_t d = base + B_OFF + row * 64 + ((kc ^ ((row >> 1) & 3)) << 4);
                CP_ASYNC16(d, WIH + (size_t)row * EDIM + k0 + kc * 8);
            }
        } else {
            const int k0 = (ch - 8) * 32;
            {   int r = tid >> 2, kc = tid & 3;
                uint32_t d = base + r * 64 + (((kc ^ ((r >> 1) & 3))) << 4);
                CP_ASYNC16(d, Hc + r * HDIM + k0 + kc * 8); }
            #pragma unroll
            for (int i = 0; i < 2; i++) {
                int s = tid + i * 512;
                int row = s >> 2, kc = s & 3;
                uint32_t d = base + B_OFF + row * 64 + ((kc ^ ((row >> 1) & 3)) << 4);
                CP_ASYNC16(d, WHH + (size_t)row * HDIM + k0 + kc * 8);
            }
        }
    };

    auto compute_chunk = [&](uint32_t st) {
        #pragma unroll
        for (int kk = 0; kk < 2; kk++) {
            const uint32_t ax = kk ? axk1 : axk0;
            const uint32_t bx = kk ? bxk1 : bxk0;
            uint32_t Ah[2][4], Bh[4][4];
            ldsm4(Ah[0], st + aBase + ax);
            ldsm4(Ah[1], st + aBase + 1024 + ax);
            #pragma unroll
            for (int nq = 0; nq < 4; nq++) ldsm4(Bh[nq], st + bBase + nq * 1024 + bx);
            #pragma unroll
            for (int mf = 0; mf < 2; mf++)
                #pragma unroll
                for (int nf = 0; nf < 8; nf++)
                    mma16816(C[mf][nf], Ah[mf], &Bh[nf >> 1][(nf & 1) * 2]);
        }
    };

    // bootstrap: tokens for step 0, prefill x chunks 0-3 (pairs 0, 1)
    {
        const int u0 = dir ? (SEQ - 1) : 0;
        if (tid < 128) tokS[tid] = docs[(n0 + tid) * SEQ + u0];
        __syncthreads();
        fill_chunk(0, tokS, (const __half*)0); fill_chunk(1, tokS, (const __half*)0); CP_COMMIT();
        fill_chunk(2, tokS, (const __half*)0); fill_chunk(3, tokS, (const __half*)0); CP_COMMIT();
    }

    #pragma unroll 1
    for (int step = 0; step < SEQ; step++) {
        const int u = dir ? (SEQ - 1 - step) : step;
        const __half* __restrict__ H0 = g_h16[step & 1] + (size_t)dir * NS * HDIM + (size_t)n0 * HDIM;
        const int* tokC = tokS + (step & 1) * 128;

        #pragma unroll
        for (int a = 0; a < 2; a++)
            #pragma unroll
            for (int b = 0; b < 8; b++)
                #pragma unroll
                for (int q = 0; q < 4; q++) C[a][b][q] = 0.f;

        // 12 windows of 2 chunks. SAFE ORDER: wait(pair p) -> barrier ->
        // fill(pair p+2) -> compute(pair p). Fill targets stages (2p-2,2p-1)%6,
        // disjoint from this window's read stages (2p,2p+1)%6; no thread can be
        // in window p-1 (all passed this window's barrier).
        #pragma unroll 1
        for (int p = 0; p < 12; p++) {
            if (p < 11) { CP_WAIT(1); } else { CP_WAIT(0); }
            __syncthreads();
            if (p < 10) {
                fill_chunk(2 * p + 4, tokC, H0);
                fill_chunk(2 * p + 5, tokC, H0);
                CP_COMMIT();
            }
            compute_chunk(sb + (uint32_t)((2 * p)     % NSTG) * ST_SZ);
            compute_chunk(sb + (uint32_t)((2 * p + 1) % NSTG) * ST_SZ);
        }

        // ---- epilogue phase A: gates -> c/pool (smem), h -> hS ----
        // (hS aliases stages 0-1; last readers were window 9, all threads passed
        //  barriers at windows 10 and 11)
        #pragma unroll
        for (int mf = 0; mf < 2; mf++) {
            #pragma unroll
            for (int rh = 0; rh < 2; rh++) {
                const int rl = mw * 32 + mf * 16 + qr + rh * 8;
                const bool inlen = (u < lenS[rl]);
                #pragma unroll
                for (int nf = 0; nf < 8; nf++) {
                    float y0 = C[mf][nf][rh * 2 + 0] + bias0[nf];
                    float y1 = C[mf][nf][rh * 2 + 1] + bias1[nf];
                    float o0 = __shfl_xor_sync(0xffffffffu, y0, 1);
                    float o1 = __shfl_xor_sync(0xffffffffu, y1, 1);
                    if (!odd) {
                        float si = 1.f / (1.f + __expf(-y0));
                        float sf = 1.f / (1.f + __expf(-y1));
                        float so = 1.f / (1.f + __expf(-o1));
                        float tg = __tanhf(o0);
                        int jl = (nw * 64 + nf * 8 + c2) >> 2;
                        float c = sf * cS[rl * 68 + jl] + si * tg;
                        float h = so * __tanhf(c);
                        cS[rl * 68 + jl] = c;
                        if (inlen) pS[rl * 68 + jl] += h;
                        hS[rl * 68 + jl] = h;
                    }
                }
            }
        }
        __syncthreads();

        // ---- epilogue phase B: coalesced h store + next-step tokens ----
        __half* __restrict__ NH = g_h16[(step + 1) & 1] + (size_t)dir * NS * HDIM;
        #pragma unroll
        for (int i = 0; i < 4; i++) {
            int idx = tid + i * 512;
            int r = idx >> 4, q = idx & 15;
            float4 hv = *(float4*)&hS[r * 68 + q * 4];
            *(uint2*)&NH[(size_t)(n0 + r) * HDIM + j0 + q * 4] =
                make_uint2(pack_hi2(hv.x, hv.y), pack_hi2(hv.z, hv.w));
        }
        if (step + 1 < SEQ && tid < 128) {
            const int un = dir ? (SEQ - 2 - step) : (step + 1);
            tokS[((step + 1) & 1) * 128 + tid] = docs[(n0 + tid) * SEQ + un];
        }
        __syncthreads();   // hS reads + token writes complete before prefill overwrites stages 0-3

        if (step + 1 < SEQ) {
            // prefill next step's x chunks 0-3 BEFORE the grid sync (independent of h)
            const int* tokN = tokS + ((step + 1) & 1) * 128;
            fill_chunk(0, tokN, (const __half*)0); fill_chunk(1, tokN, (const __half*)0); CP_COMMIT();
            fill_chunk(2, tokN, (const __half*)0); fill_chunk(3, tokN, (const __half*)0); CP_COMMIT();

            // grid sync: release h writes, acquire all CTAs' h (gathers land during spin)
            if (tid == 0) {
                __threadfence();
                atomicAdd(&g_sync, 1u);
                unsigned target = 128u * (unsigned)(step + 1);
                while (*(volatile unsigned*)&g_sync < target) __nanosleep(64);
                __threadfence();
            }
            __syncthreads();
        }
    }

    // ---- final: pool/len, doc mask, write out slice ----
    #pragma unroll 1
    for (int i = tid; i < 128 * 16; i += 512) {
        int r = i >> 4, q = i & 15;
        int nd = n0 + r;
        int b = nd >> 5, d = nd & 31;
        float4 v = make_float4(0.f, 0.f, 0.f, 0.f);
        if (d < doc_lens[b]) {
            int len = lenS[r];
            float inv = 1.f / (float)(len > 0 ? len : 1);
            float4 pv = *(float4*)&pS[r * 68 + q * 4];
            v = make_float4(pv.x * inv, pv.y * inv, pv.z * inv, pv.w * inv);
        }
        *(float4*)&out[(size_t)nd * 1024 + dir * 512 + j0 + q * 4] = v;
    }
}

extern "C" void kernel_launch(void* const* d_in, const int* in_sizes, int n_in,
                              void* d_out, int out_size)
{
    const int* docs     = (const int*)d_in[0];
    const int* doc_lens = (const int*)d_in[1];
    int base = (n_in >= 10 && in_sizes[2] == 1) ? 3 : 2;
    const float* emb   = (const float*)d_in[base + 0];
    const float* wih_f = (const float*)d_in[base + 1];
    const float* whh_f = (const float*)d_in[base + 2];
    const float* b_f   = (const float*)d_in[base + 3];
    const float* wih_b = (const float*)d_in[base + 4];
    const float* whh_b = (const float*)d_in[base + 5];
    const float* b_b   = (const float*)d_in[base + 6];
    float* out = (float*)d_out;

    cudaFuncSetAttribute(k_persist, cudaFuncAttributeMaxDynamicSharedMemorySize, SMEM_SZ);

    k_prep   <<<15168, 256>>>(docs, emb, wih_f, wih_b, whh_f, whh_b);
    k_persist<<<dim3(8, 8, 2), 512, SMEM_SZ>>>(docs, doc_lens, b_f, b_b, out);
}